// round 15
// baseline (speedup 1.0000x reference)
#include <cuda_runtime.h>
#include <cuda_fp16.h>
#include <math.h>
#include <stdint.h>

// ---------------------------------------------------------------------------
// Scratch (no cudaMalloc allowed)
// ---------------------------------------------------------------------------
__device__ __align__(128) __half g_xh  [8192u * 768u];       // x, fp16
__device__ __align__(128) __half g_wqh [2304u * 768u];       // W_qkv^T, fp16
__device__ __align__(128) __half g_wph [768u * 768u];        // W_proj^T, fp16
__device__ __align__(128) __half g_qkvh[2u * 4096u * 2304u]; // QKV fp16 (Q pre-scaled)
__device__ __align__(128) __half g_atth[8192u * 768u];       // attention out, fp16

// ---------------------------------------------------------------------------
// PTX helpers
// ---------------------------------------------------------------------------
__device__ __forceinline__ uint32_t smem_u32(const void* p) {
    uint32_t a;
    asm("{ .reg .u64 t; cvta.to.shared.u64 t, %1; cvt.u32.u64 %0, t; }"
        : "=r"(a) : "l"(p));
    return a;
}

#define CP_ASYNC16(dst, src) \
    asm volatile("cp.async.cg.shared.global [%0], [%1], 16;" :: "r"(dst), "l"(src))
#define CP_COMMIT() asm volatile("cp.async.commit_group;" ::: "memory")
#define CP_WAIT(n)  asm volatile("cp.async.wait_group %0;" :: "n"(n) : "memory")

// m16n8k16 fp16 mma, fp32 accum, D += A*B
__device__ __forceinline__ void mma16(float c[4], const uint32_t a[4], const uint32_t b[2]) {
    asm volatile(
        "mma.sync.aligned.m16n8k16.row.col.f32.f16.f16.f32 "
        "{%0,%1,%2,%3}, {%4,%5,%6,%7}, {%8,%9}, {%0,%1,%2,%3};"
        : "+f"(c[0]), "+f"(c[1]), "+f"(c[2]), "+f"(c[3])
        : "r"(a[0]), "r"(a[1]), "r"(a[2]), "r"(a[3]), "r"(b[0]), "r"(b[1]));
}

#define LDSM_X4(r0, r1, r2, r3, addr) \
    asm volatile("ldmatrix.sync.aligned.m8n8.x4.shared.b16 {%0,%1,%2,%3}, [%4];" \
                 : "=r"(r0), "=r"(r1), "=r"(r2), "=r"(r3) : "r"(addr))
#define LDSM_X4_T(r0, r1, r2, r3, addr) \
    asm volatile("ldmatrix.sync.aligned.m8n8.x4.trans.shared.b16 {%0,%1,%2,%3}, [%4];" \
                 : "=r"(r0), "=r"(r1), "=r"(r2), "=r"(r3) : "r"(addr))

__device__ __forceinline__ uint32_t packh2(float lo, float hi) {
    __half2 h = __floats2half2_rn(lo, hi);
    return *reinterpret_cast<uint32_t*>(&h);
}
// packed half2 exp2
__device__ __forceinline__ uint32_t ex2h2(uint32_t x) {
    uint32_t r; asm("ex2.approx.f16x2 %0, %1;" : "=r"(r) : "r"(x)); return r;
}

// ---------------------------------------------------------------------------
// Prep kernels
// ---------------------------------------------------------------------------
__global__ __launch_bounds__(256) void conv_half_k(
    const float* __restrict__ src, __half* __restrict__ dst, int n4)
{
    int i = blockIdx.x * 256 + threadIdx.x;
    if (i < n4) {
        float4 v = *(const float4*)(src + 4 * (size_t)i);
        *(uint2*)(dst + 4 * (size_t)i) = make_uint2(packh2(v.x, v.y), packh2(v.z, v.w));
    }
}

// W [K][N] fp32 -> WT [N][K] fp16
__global__ __launch_bounds__(256) void transp_half_k(
    const float* __restrict__ W, __half* __restrict__ WT, int K, int N)
{
    __shared__ float t[32][33];
    const int n0 = blockIdx.x * 32, k0 = blockIdx.y * 32;
    const int x = threadIdx.x & 31, y = threadIdx.x >> 5;
#pragma unroll
    for (int j = 0; j < 32; j += 8)
        t[y + j][x] = W[(size_t)(k0 + y + j) * N + (n0 + x)];
    __syncthreads();
#pragma unroll
    for (int j = 0; j < 32; j += 8)
        WT[(size_t)(n0 + y + j) * K + (k0 + x)] = __float2half_rn(t[x][y + j]);
}

// ---------------------------------------------------------------------------
// fp16 GEMM (unchanged from R11): C[M,N] = Ah[M,K] @ BhT[N,K]^T + bias
// ---------------------------------------------------------------------------
static constexpr int G_STAGE = 36864;             // (128+128) rows * 144 B
static constexpr int GEMM_SMEM = 3 * G_STAGE;     // 110592 B
static constexpr float QSCALE = 0.125f * 1.44269504088896340736f;

__global__ __launch_bounds__(256, 2) void gemm_h(
    const __half* __restrict__ Ah, const __half* __restrict__ Bh,
    const float* __restrict__ bias, float* __restrict__ Cf,
    __half* __restrict__ Ch, int M, int N, int K, int qlim)
{
    extern __shared__ char smc[];
    const uint32_t sb = smem_u32(smc);
    const int tid  = threadIdx.x;
    const int wid  = tid >> 5;
    const int lane = tid & 31;
    const int g    = lane >> 2;
    const int tig  = lane & 3;
    const int wm   = wid & 3;
    const int wn   = wid >> 2;
    const int m0   = blockIdx.y * 128;
    const int n0   = blockIdx.x * 128;

    const int nk = K >> 6;          // BK = 64

    auto stage = [&](int kt, int s) {
        const uint32_t base = sb + s * G_STAGE;
#pragma unroll
        for (int i = 0; i < 8; i++) {
            int q = tid + 256 * i;
            int r = (q & 1023) >> 3;
            int c = q & 7;
            if (q < 1024)
                CP_ASYNC16(base + r * 144 + c * 16,
                           Ah + (size_t)(m0 + r) * K + kt * 64 + c * 8);
            else
                CP_ASYNC16(base + 18432 + r * 144 + c * 16,
                           Bh + (size_t)(n0 + r) * K + kt * 64 + c * 8);
        }
    };

    float acc[2][8][4];
#pragma unroll
    for (int mt = 0; mt < 2; mt++)
#pragma unroll
        for (int nt = 0; nt < 8; nt++)
#pragma unroll
            for (int c = 0; c < 4; c++) acc[mt][nt][c] = 0.0f;

    stage(0, 0); CP_COMMIT();
    stage(1, 1); CP_COMMIT();

    const int lrow = lane & 15;
    const int lsel = lane >> 4;

#pragma unroll 3
    for (int kt = 0; kt < nk; kt++) {
        CP_WAIT(1);
        __syncthreads();

        const uint32_t Ab = sb + (kt % 3) * G_STAGE;
        const uint32_t Bb = Ab + 18432;

        uint32_t af[2][2][4];
        uint32_t bf[2][4];

        LDSM_X4(af[0][0][0], af[0][0][1], af[0][0][2], af[0][0][3],
                Ab + (wm * 32 + lrow) * 144 + lsel * 16);
        LDSM_X4(af[0][1][0], af[0][1][1], af[0][1][2], af[0][1][3],
                Ab + (wm * 32 + 16 + lrow) * 144 + lsel * 16);
        LDSM_X4(bf[0][0], bf[0][1], bf[0][2], bf[0][3],
                Bb + (wn * 64 + lrow) * 144 + lsel * 16);

        if (kt + 2 < nk) stage(kt + 2, (kt + 2) % 3);
        CP_COMMIT();

#pragma unroll
        for (int i = 0; i < 16; i++) {
            const int kk  = i >> 2, ntp = i & 3;
            const int cur = i & 1,  nxt = cur ^ 1;
            if (i < 15) {
                const int kn = (i + 1) >> 2, np = (i + 1) & 3;
                LDSM_X4(bf[nxt][0], bf[nxt][1], bf[nxt][2], bf[nxt][3],
                        Bb + (wn * 64 + np * 16 + lrow) * 144 + (kn * 2 + lsel) * 16);
            }
            if (ntp == 2 && kk < 3) {
                const int ka = kk + 1, pa = ka & 1;
                LDSM_X4(af[pa][0][0], af[pa][0][1], af[pa][0][2], af[pa][0][3],
                        Ab + (wm * 32 + lrow) * 144 + (ka * 2 + lsel) * 16);
                LDSM_X4(af[pa][1][0], af[pa][1][1], af[pa][1][2], af[pa][1][3],
                        Ab + (wm * 32 + 16 + lrow) * 144 + (ka * 2 + lsel) * 16);
            }
            uint32_t be[2] = {bf[cur][0], bf[cur][2]};
            uint32_t bo[2] = {bf[cur][1], bf[cur][3]};
            mma16(acc[0][2 * ntp],     af[kk & 1][0], be);
            mma16(acc[0][2 * ntp + 1], af[kk & 1][0], bo);
            mma16(acc[1][2 * ntp],     af[kk & 1][1], be);
            mma16(acc[1][2 * ntp + 1], af[kk & 1][1], bo);
        }
    }

    // ---- epilogue ----
#pragma unroll
    for (int mt = 0; mt < 2; mt++) {
        const int r = m0 + wm * 32 + mt * 16 + g;
#pragma unroll
        for (int nt = 0; nt < 8; nt++) {
            const int col = n0 + wn * 64 + nt * 8 + 2 * tig;
            const float b0 = bias[col], b1 = bias[col + 1];
            float v0 = acc[mt][nt][0] + b0, v1 = acc[mt][nt][1] + b1;
            float v2 = acc[mt][nt][2] + b0, v3 = acc[mt][nt][3] + b1;
            if (col < qlim) { v0 *= QSCALE; v1 *= QSCALE; v2 *= QSCALE; v3 *= QSCALE; }
            if (Ch) {
                *(uint32_t*)(Ch + (size_t)r * N + col)       = packh2(v0, v1);
                *(uint32_t*)(Ch + (size_t)(r + 8) * N + col) = packh2(v2, v3);
            } else {
                *(float2*)(Cf + (size_t)r * N + col)       = make_float2(v0, v1);
                *(float2*)(Cf + (size_t)(r + 8) * N + col) = make_float2(v2, v3);
            }
        }
    }
}

// ---------------------------------------------------------------------------
// Causal flash attention, fp16 mma.sync, no online max, PV(kt-1) deferred.
// NEW: warp m-tile = 32 q-rows (mt=2) -> each K/V ldmatrix fragment feeds
// 4 MMAs instead of 2, HALVING smem crossbar traffic per MMA (the measured
// bottleneck). BM=256, 8 warps, 256 threads, 1 CTA/SM (255 regs).
// Q fragments register-resident for the whole kernel. Row sums via MMA
// against all-ones B fragment. 4-slot K/V cp.async ring.
// ---------------------------------------------------------------------------
static constexpr int Q_OFF  = 0;          // 256*144 = 36864 B
static constexpr int KV_OFF = 36864;      // 4 slots of (K 9216 + V 9216)
static constexpr int ATT_SMEM = 36864 + 4 * 18432;   // 110592 B

__global__ __launch_bounds__(256, 1) void flash_h(
    const __half* __restrict__ qkv, __half* __restrict__ out)
{
    extern __shared__ char smc[];
    const uint32_t sb = smem_u32(smc);
    const int tid  = threadIdx.x;
    const int wid  = tid >> 5;
    const int lane = tid & 31;
    const int g    = lane >> 2;
    const int tig  = lane & 3;
    const int lrow = lane & 15;
    const int lsel = lane >> 4;
    const int qb   = gridDim.x - 1 - blockIdx.x;   // big blocks first
    const int t0   = qb * 256;
    const int h    = blockIdx.y;
    const int b    = blockIdx.z;

    const int D3 = 2304;
    const __half* qp = qkv + (size_t)b * 4096 * D3 + h * 64;   // Q pre-scaled
    const __half* kp = qp + 768;
    const __half* vp = qp + 1536;

    const uint32_t bones[2] = {0x3C003C00u, 0x3C003C00u};      // all-ones B frag

    auto stage_kv = [&](int kt, int s) {
        const int j0 = kt * 64;
        const uint32_t base = sb + KV_OFF + s * 18432;
#pragma unroll
        for (int i = 0; i < 4; i++) {
            int q = tid + 256 * i;
            int rr = (q & 511) >> 3, c = q & 7;
            if (q < 512)
                CP_ASYNC16(base + rr * 144 + c * 16,
                           kp + (size_t)(j0 + rr) * D3 + c * 8);
            else
                CP_ASYNC16(base + 9216 + rr * 144 + c * 16,
                           vp + (size_t)(j0 + rr) * D3 + c * 8);
        }
    };

    // ---- prologue: stage Q (256 rows) + tile0, then tile1 ----
#pragma unroll
    for (int i = 0; i < 8; i++) {
        int q = tid + 256 * i;
        int r = q >> 3, c = q & 7;
        CP_ASYNC16(sb + Q_OFF + r * 144 + c * 16,
                   qp + (size_t)(t0 + r) * D3 + c * 8);
    }
    stage_kv(0, 0);
    CP_COMMIT();
    stage_kv(1, 1);
    CP_COMMIT();

    float oacc[2][8][4];
#pragma unroll
    for (int mt = 0; mt < 2; mt++)
#pragma unroll
        for (int nt = 0; nt < 8; nt++)
#pragma unroll
            for (int c = 0; c < 4; c++) oacc[mt][nt][c] = 0.0f;
    float lacc[2][4];
#pragma unroll
    for (int mt = 0; mt < 2; mt++)
#pragma unroll
        for (int c = 0; c < 4; c++) lacc[mt][c] = 0.0f;
    uint32_t pa_prev[2][16];    // P fragments of tile kt-1, per m-tile
    uint32_t qf[2][4][4];       // Q fragments, resident whole kernel

    const int ntiles = 4 * qb + 4;
    for (int kt = 0; kt < ntiles; kt++) {
        CP_WAIT(1);          // tile kt (and Q on kt=0) complete
        __syncthreads();

        // ---- 0) one-time Q fragment hoist (Q never changes) ----
        if (kt == 0) {
#pragma unroll
            for (int mt = 0; mt < 2; mt++)
#pragma unroll
                for (int kk = 0; kk < 4; kk++)
                    LDSM_X4(qf[mt][kk][0], qf[mt][kk][1], qf[mt][kk][2], qf[mt][kk][3],
                            sb + Q_OFF + (wid * 32 + mt * 16 + lrow) * 144
                               + (kk * 2 + lsel) * 16);
        }

        // ---- 1) deferred O/l += P(kt-1) @ [V(kt-1) | 1]; each V fragment
        //         feeds 4 MMAs (both m-tiles) ----
        if (kt > 0) {
            const uint32_t Vprev = sb + KV_OFF + ((kt - 1) & 3) * 18432 + 9216;
#pragma unroll
            for (int kk = 0; kk < 4; kk++) {
                const uint32_t vaddr = Vprev + (kk * 16 + lrow) * 144 + lsel * 16;
#pragma unroll
                for (int ntp = 0; ntp < 4; ntp++) {
                    uint32_t b0, b1, b2, b3;
                    LDSM_X4_T(b0, b1, b2, b3, vaddr + ntp * 32);
                    uint32_t be[2] = {b0, b1}, bo[2] = {b2, b3};
                    mma16(oacc[0][2 * ntp],     &pa_prev[0][kk * 4], be);
                    mma16(oacc[0][2 * ntp + 1], &pa_prev[0][kk * 4], bo);
                    mma16(oacc[1][2 * ntp],     &pa_prev[1][kk * 4], be);
                    mma16(oacc[1][2 * ntp + 1], &pa_prev[1][kk * 4], bo);
                }
                mma16(lacc[0], &pa_prev[0][kk * 4], bones);
                mma16(lacc[1], &pa_prev[1][kk * 4], bones);
            }
        }

        // ---- 2) stage tile kt+2 (DMA overlaps the QK MMAs below) ----
        if (kt + 2 < ntiles) stage_kv(kt + 2, (kt + 2) & 3);
        CP_COMMIT();

        // ---- 3) S = Q @ K^T; each K fragment feeds 4 MMAs (both m-tiles) ----
        const uint32_t Kb = sb + KV_OFF + (kt & 3) * 18432;
        float sacc[2][8][4];
#pragma unroll
        for (int mt = 0; mt < 2; mt++)
#pragma unroll
            for (int nt = 0; nt < 8; nt++)
#pragma unroll
                for (int c = 0; c < 4; c++) sacc[mt][nt][c] = 0.0f;

#pragma unroll
        for (int kk = 0; kk < 4; kk++) {
            const int cc = (kk * 2 + lsel) * 16;
#pragma unroll
            for (int ntp = 0; ntp < 4; ntp++) {
                uint32_t b0, b1, b2, b3;
                LDSM_X4(b0, b1, b2, b3, Kb + (ntp * 16 + lrow) * 144 + cc);
                uint32_t be[2] = {b0, b2}, bo[2] = {b1, b3};
                mma16(sacc[0][2 * ntp],     qf[0][kk], be);
                mma16(sacc[0][2 * ntp + 1], qf[0][kk], bo);
                mma16(sacc[1][2 * ntp],     qf[1][kk], be);
                mma16(sacc[1][2 * ntp + 1], qf[1][kk], bo);
            }
        }

        // ---- 4) causal mask (last 4 tiles intersect the 256-row diagonal) ----
        if (kt >= ntiles - 4) {
            const int j0 = kt * 64;
#pragma unroll
            for (int mt = 0; mt < 2; mt++) {
                const int r0 = t0 + wid * 32 + mt * 16 + g;
                const int r1 = r0 + 8;
#pragma unroll
                for (int nt = 0; nt < 8; nt++) {
                    int c = j0 + nt * 8 + 2 * tig;
                    if (c     > r0) sacc[mt][nt][0] = -INFINITY;
                    if (c + 1 > r0) sacc[mt][nt][1] = -INFINITY;
                    if (c     > r1) sacc[mt][nt][2] = -INFINITY;
                    if (c + 1 > r1) sacc[mt][nt][3] = -INFINITY;
                }
            }
        }

        // ---- 5) P(kt) = exp2(S) straight into fp16 A-fragments (no max) ----
#pragma unroll
        for (int mt = 0; mt < 2; mt++)
#pragma unroll
            for (int kk = 0; kk < 4; kk++) {
                pa_prev[mt][kk*4+0] = ex2h2(packh2(sacc[mt][2*kk][0],   sacc[mt][2*kk][1]));
                pa_prev[mt][kk*4+1] = ex2h2(packh2(sacc[mt][2*kk][2],   sacc[mt][2*kk][3]));
                pa_prev[mt][kk*4+2] = ex2h2(packh2(sacc[mt][2*kk+1][0], sacc[mt][2*kk+1][1]));
                pa_prev[mt][kk*4+3] = ex2h2(packh2(sacc[mt][2*kk+1][2], sacc[mt][2*kk+1][3]));
            }
    }

    // ---- trailing PV + row sums for the last tile ----
    {
        const uint32_t Vlast = sb + KV_OFF + ((ntiles - 1) & 3) * 18432 + 9216;
#pragma unroll
        for (int kk = 0; kk < 4; kk++) {
            const uint32_t vaddr = Vlast + (kk * 16 + lrow) * 144 + lsel * 16;
#pragma unroll
            for (int ntp = 0; ntp < 4; ntp++) {
                uint32_t b0, b1, b2, b3;
                LDSM_X4_T(b0, b1, b2, b3, vaddr + ntp * 32);
                uint32_t be[2] = {b0, b1}, bo[2] = {b2, b3};
                mma16(oacc[0][2 * ntp],     &pa_prev[0][kk * 4], be);
                mma16(oacc[0][2 * ntp + 1], &pa_prev[0][kk * 4], bo);
                mma16(oacc[1][2 * ntp],     &pa_prev[1][kk * 4], be);
                mma16(oacc[1][2 * ntp + 1], &pa_prev[1][kk * 4], bo);
            }
            mma16(lacc[0], &pa_prev[0][kk * 4], bones);
            mma16(lacc[1], &pa_prev[1][kk * 4], bones);
        }
    }

    // ---- epilogue: normalize, write fp16 [B,T,D] ----
    __half* ob = out + (size_t)b * 4096 * 768;
#pragma unroll
    for (int mt = 0; mt < 2; mt++) {
        const float i0 = 1.0f / lacc[mt][0];
        const float i1 = 1.0f / lacc[mt][2];
        const int r0 = t0 + wid * 32 + mt * 16 + g;
#pragma unroll
        for (int nt = 0; nt < 8; nt++) {
            const int c = h * 64 + nt * 8 + 2 * tig;
            *(uint32_t*)(ob + (size_t)r0 * 768 + c) =
                packh2(oacc[mt][nt][0] * i0, oacc[mt][nt][1] * i0);
            *(uint32_t*)(ob + (size_t)(r0 + 8) * 768 + c) =
                packh2(oacc[mt][nt][2] * i1, oacc[mt][nt][3] * i1);
        }
    }
}

// ---------------------------------------------------------------------------
// Launch
// ---------------------------------------------------------------------------
extern "C" void kernel_launch(void* const* d_in, const int* in_sizes, int n_in,
                              void* d_out, int out_size)
{
    (void)in_sizes; (void)n_in; (void)out_size;
    const float* x     = (const float*)d_in[0];
    const float* Wqkv  = (const float*)d_in[1];
    const float* bqkv  = (const float*)d_in[2];
    const float* Wproj = (const float*)d_in[3];
    const float* bproj = (const float*)d_in[4];
    float* out = (float*)d_out;

    void *pxh, *pwq, *pwp, *pqk, *pat;
    cudaGetSymbolAddress(&pxh, g_xh);
    cudaGetSymbolAddress(&pwq, g_wqh);
    cudaGetSymbolAddress(&pwp, g_wph);
    cudaGetSymbolAddress(&pqk, g_qkvh);
    cudaGetSymbolAddress(&pat, g_atth);
    __half* xh   = (__half*)pxh;
    __half* wqh  = (__half*)pwq;
    __half* wph  = (__half*)pwp;
    __half* qkvh = (__half*)pqk;
    __half* atth = (__half*)pat;

    cudaFuncSetAttribute(gemm_h,
                         cudaFuncAttributeMaxDynamicSharedMemorySize, GEMM_SMEM);
    cudaFuncSetAttribute(flash_h,
                         cudaFuncAttributeMaxDynamicSharedMemorySize, ATT_SMEM);

    // 0) fp16 prep: convert x, transpose+convert weights
    conv_half_k<<<(8192 * 768 / 4 + 255) / 256, 256>>>(x, xh, 8192 * 768 / 4);
    transp_half_k<<<dim3(2304 / 32, 768 / 32), 256>>>(Wqkv,  wqh, 768, 2304);
    transp_half_k<<<dim3(768 / 32,  768 / 32), 256>>>(Wproj, wph, 768, 768);

    // 1) QKV = x @ W_qkv + b_qkv -> fp16 (Q slice pre-scaled by 0.125*log2e)
    gemm_h<<<dim3(2304 / 128, 8192 / 128), 256, GEMM_SMEM>>>(
        xh, wqh, bqkv, nullptr, qkvh, 8192, 2304, 768, 768);

    // 2) causal attention -> fp16 (BM=256 q-rows per CTA)
    flash_h<<<dim3(16, 12, 2), 256, ATT_SMEM>>>(qkvh, atth);

    // 3) out = attn @ W_proj + b_proj -> fp32
    gemm_h<<<dim3(768 / 128, 8192 / 128), 256, GEMM_SMEM>>>(
        atth, wph, bproj, out, nullptr, 8192, 768, 768, 0);
}

// round 16
// speedup vs baseline: 1.0766x; 1.0766x over previous
#include <cuda_runtime.h>
#include <cuda_fp16.h>
#include <math.h>
#include <stdint.h>

// ---------------------------------------------------------------------------
// Scratch (no cudaMalloc allowed)
// ---------------------------------------------------------------------------
__device__ __align__(128) __half g_xh  [8192u * 768u];       // x, fp16
__device__ __align__(128) __half g_wqh [2304u * 768u];       // W_qkv^T, fp16
__device__ __align__(128) __half g_wph [768u * 768u];        // W_proj^T, fp16
__device__ __align__(128) __half g_qkvh[2u * 4096u * 2304u]; // QKV fp16 (Q pre-scaled)
__device__ __align__(128) __half g_atth[8192u * 768u];       // attention out, fp16

// ---------------------------------------------------------------------------
// PTX helpers
// ---------------------------------------------------------------------------
__device__ __forceinline__ uint32_t smem_u32(const void* p) {
    uint32_t a;
    asm("{ .reg .u64 t; cvta.to.shared.u64 t, %1; cvt.u32.u64 %0, t; }"
        : "=r"(a) : "l"(p));
    return a;
}

#define CP_ASYNC16(dst, src) \
    asm volatile("cp.async.cg.shared.global [%0], [%1], 16;" :: "r"(dst), "l"(src))
#define CP_COMMIT() asm volatile("cp.async.commit_group;" ::: "memory")
#define CP_WAIT(n)  asm volatile("cp.async.wait_group %0;" :: "n"(n) : "memory")

// m16n8k16 fp16 mma, fp32 accum, D += A*B
__device__ __forceinline__ void mma16(float c[4], const uint32_t a[4], const uint32_t b[2]) {
    asm volatile(
        "mma.sync.aligned.m16n8k16.row.col.f32.f16.f16.f32 "
        "{%0,%1,%2,%3}, {%4,%5,%6,%7}, {%8,%9}, {%0,%1,%2,%3};"
        : "+f"(c[0]), "+f"(c[1]), "+f"(c[2]), "+f"(c[3])
        : "r"(a[0]), "r"(a[1]), "r"(a[2]), "r"(a[3]), "r"(b[0]), "r"(b[1]));
}

#define LDSM_X4(r0, r1, r2, r3, addr) \
    asm volatile("ldmatrix.sync.aligned.m8n8.x4.shared.b16 {%0,%1,%2,%3}, [%4];" \
                 : "=r"(r0), "=r"(r1), "=r"(r2), "=r"(r3) : "r"(addr))
#define LDSM_X4_T(r0, r1, r2, r3, addr) \
    asm volatile("ldmatrix.sync.aligned.m8n8.x4.trans.shared.b16 {%0,%1,%2,%3}, [%4];" \
                 : "=r"(r0), "=r"(r1), "=r"(r2), "=r"(r3) : "r"(addr))

__device__ __forceinline__ uint32_t packh2(float lo, float hi) {
    __half2 h = __floats2half2_rn(lo, hi);
    return *reinterpret_cast<uint32_t*>(&h);
}
// packed half2 exp2
__device__ __forceinline__ uint32_t ex2h2(uint32_t x) {
    uint32_t r; asm("ex2.approx.f16x2 %0, %1;" : "=r"(r) : "r"(x)); return r;
}

// ---------------------------------------------------------------------------
// Prep kernels
// ---------------------------------------------------------------------------
__global__ __launch_bounds__(256) void conv_half_k(
    const float* __restrict__ src, __half* __restrict__ dst, int n4)
{
    int i = blockIdx.x * 256 + threadIdx.x;
    if (i < n4) {
        float4 v = *(const float4*)(src + 4 * (size_t)i);
        *(uint2*)(dst + 4 * (size_t)i) = make_uint2(packh2(v.x, v.y), packh2(v.z, v.w));
    }
}

// W [K][N] fp32 -> WT [N][K] fp16
__global__ __launch_bounds__(256) void transp_half_k(
    const float* __restrict__ W, __half* __restrict__ WT, int K, int N)
{
    __shared__ float t[32][33];
    const int n0 = blockIdx.x * 32, k0 = blockIdx.y * 32;
    const int x = threadIdx.x & 31, y = threadIdx.x >> 5;
#pragma unroll
    for (int j = 0; j < 32; j += 8)
        t[y + j][x] = W[(size_t)(k0 + y + j) * N + (n0 + x)];
    __syncthreads();
#pragma unroll
    for (int j = 0; j < 32; j += 8)
        WT[(size_t)(n0 + y + j) * K + (k0 + x)] = __float2half_rn(t[x][y + j]);
}

// ---------------------------------------------------------------------------
// fp16 GEMM (unchanged, best known): C[M,N] = Ah[M,K] @ BhT[N,K]^T + bias
// ---------------------------------------------------------------------------
static constexpr int G_STAGE = 36864;             // (128+128) rows * 144 B
static constexpr int GEMM_SMEM = 3 * G_STAGE;     // 110592 B
static constexpr float QSCALE = 0.125f * 1.44269504088896340736f;

__global__ __launch_bounds__(256, 2) void gemm_h(
    const __half* __restrict__ Ah, const __half* __restrict__ Bh,
    const float* __restrict__ bias, float* __restrict__ Cf,
    __half* __restrict__ Ch, int M, int N, int K, int qlim)
{
    extern __shared__ char smc[];
    const uint32_t sb = smem_u32(smc);
    const int tid  = threadIdx.x;
    const int wid  = tid >> 5;
    const int lane = tid & 31;
    const int g    = lane >> 2;
    const int tig  = lane & 3;
    const int wm   = wid & 3;
    const int wn   = wid >> 2;
    const int m0   = blockIdx.y * 128;
    const int n0   = blockIdx.x * 128;

    const int nk = K >> 6;          // BK = 64

    auto stage = [&](int kt, int s) {
        const uint32_t base = sb + s * G_STAGE;
#pragma unroll
        for (int i = 0; i < 8; i++) {
            int q = tid + 256 * i;
            int r = (q & 1023) >> 3;
            int c = q & 7;
            if (q < 1024)
                CP_ASYNC16(base + r * 144 + c * 16,
                           Ah + (size_t)(m0 + r) * K + kt * 64 + c * 8);
            else
                CP_ASYNC16(base + 18432 + r * 144 + c * 16,
                           Bh + (size_t)(n0 + r) * K + kt * 64 + c * 8);
        }
    };

    float acc[2][8][4];
#pragma unroll
    for (int mt = 0; mt < 2; mt++)
#pragma unroll
        for (int nt = 0; nt < 8; nt++)
#pragma unroll
            for (int c = 0; c < 4; c++) acc[mt][nt][c] = 0.0f;

    stage(0, 0); CP_COMMIT();
    stage(1, 1); CP_COMMIT();

    const int lrow = lane & 15;
    const int lsel = lane >> 4;

#pragma unroll 3
    for (int kt = 0; kt < nk; kt++) {
        CP_WAIT(1);
        __syncthreads();

        const uint32_t Ab = sb + (kt % 3) * G_STAGE;
        const uint32_t Bb = Ab + 18432;

        uint32_t af[2][2][4];
        uint32_t bf[2][4];

        LDSM_X4(af[0][0][0], af[0][0][1], af[0][0][2], af[0][0][3],
                Ab + (wm * 32 + lrow) * 144 + lsel * 16);
        LDSM_X4(af[0][1][0], af[0][1][1], af[0][1][2], af[0][1][3],
                Ab + (wm * 32 + 16 + lrow) * 144 + lsel * 16);
        LDSM_X4(bf[0][0], bf[0][1], bf[0][2], bf[0][3],
                Bb + (wn * 64 + lrow) * 144 + lsel * 16);

        if (kt + 2 < nk) stage(kt + 2, (kt + 2) % 3);
        CP_COMMIT();

#pragma unroll
        for (int i = 0; i < 16; i++) {
            const int kk  = i >> 2, ntp = i & 3;
            const int cur = i & 1,  nxt = cur ^ 1;
            if (i < 15) {
                const int kn = (i + 1) >> 2, np = (i + 1) & 3;
                LDSM_X4(bf[nxt][0], bf[nxt][1], bf[nxt][2], bf[nxt][3],
                        Bb + (wn * 64 + np * 16 + lrow) * 144 + (kn * 2 + lsel) * 16);
            }
            if (ntp == 2 && kk < 3) {
                const int ka = kk + 1, pa = ka & 1;
                LDSM_X4(af[pa][0][0], af[pa][0][1], af[pa][0][2], af[pa][0][3],
                        Ab + (wm * 32 + lrow) * 144 + (ka * 2 + lsel) * 16);
                LDSM_X4(af[pa][1][0], af[pa][1][1], af[pa][1][2], af[pa][1][3],
                        Ab + (wm * 32 + 16 + lrow) * 144 + (ka * 2 + lsel) * 16);
            }
            uint32_t be[2] = {bf[cur][0], bf[cur][2]};
            uint32_t bo[2] = {bf[cur][1], bf[cur][3]};
            mma16(acc[0][2 * ntp],     af[kk & 1][0], be);
            mma16(acc[0][2 * ntp + 1], af[kk & 1][0], bo);
            mma16(acc[1][2 * ntp],     af[kk & 1][1], be);
            mma16(acc[1][2 * ntp + 1], af[kk & 1][1], bo);
        }
    }

    // ---- epilogue ----
#pragma unroll
    for (int mt = 0; mt < 2; mt++) {
        const int r = m0 + wm * 32 + mt * 16 + g;
#pragma unroll
        for (int nt = 0; nt < 8; nt++) {
            const int col = n0 + wn * 64 + nt * 8 + 2 * tig;
            const float b0 = bias[col], b1 = bias[col + 1];
            float v0 = acc[mt][nt][0] + b0, v1 = acc[mt][nt][1] + b1;
            float v2 = acc[mt][nt][2] + b0, v3 = acc[mt][nt][3] + b1;
            if (col < qlim) { v0 *= QSCALE; v1 *= QSCALE; v2 *= QSCALE; v3 *= QSCALE; }
            if (Ch) {
                *(uint32_t*)(Ch + (size_t)r * N + col)       = packh2(v0, v1);
                *(uint32_t*)(Ch + (size_t)(r + 8) * N + col) = packh2(v2, v3);
            } else {
                *(float2*)(Cf + (size_t)r * N + col)       = make_float2(v0, v1);
                *(float2*)(Cf + (size_t)(r + 8) * N + col) = make_float2(v2, v3);
            }
        }
    }
}

// ---------------------------------------------------------------------------
// Causal flash attention, fp16 mma.sync, no online max, PV(kt-1) deferred.
// BM=128, 4 warps x 32 q-rows (mt=2): each K/V ldmatrix fragment feeds 4
// MMAs (half the smem traffic of the 8-warp/16-row layout), while
// __launch_bounds__(128,2) keeps 2 CTAs/SM (8 warps) for barrier overlap
// and a 255-reg budget (no spills). Q fragments register-resident.
// Row sums via MMA against all-ones B fragment. 4-slot K/V cp.async ring.
// ---------------------------------------------------------------------------
static constexpr int Q_OFF  = 0;          // 128*144 = 18432 B
static constexpr int KV_OFF = 18432;      // 4 slots of (K 9216 + V 9216)
static constexpr int ATT_SMEM = 18432 + 4 * 18432;   // 92160 B

__global__ __launch_bounds__(128, 2) void flash_h(
    const __half* __restrict__ qkv, __half* __restrict__ out)
{
    extern __shared__ char smc[];
    const uint32_t sb = smem_u32(smc);
    const int tid  = threadIdx.x;
    const int wid  = tid >> 5;          // 0..3
    const int lane = tid & 31;
    const int g    = lane >> 2;
    const int tig  = lane & 3;
    const int lrow = lane & 15;
    const int lsel = lane >> 4;
    const int qb   = gridDim.x - 1 - blockIdx.x;   // big blocks first
    const int t0   = qb * 128;
    const int h    = blockIdx.y;
    const int b    = blockIdx.z;

    const int D3 = 2304;
    const __half* qp = qkv + (size_t)b * 4096 * D3 + h * 64;   // Q pre-scaled
    const __half* kp = qp + 768;
    const __half* vp = qp + 1536;

    const uint32_t bones[2] = {0x3C003C00u, 0x3C003C00u};      // all-ones B frag

    auto stage_kv = [&](int kt, int s) {
        const int j0 = kt * 64;
        const uint32_t base = sb + KV_OFF + s * 18432;
#pragma unroll
        for (int i = 0; i < 8; i++) {
            int q = tid + 128 * i;              // 0..1023
            int rr = (q & 511) >> 3, c = q & 7;
            if (q < 512)
                CP_ASYNC16(base + rr * 144 + c * 16,
                           kp + (size_t)(j0 + rr) * D3 + c * 8);
            else
                CP_ASYNC16(base + 9216 + rr * 144 + c * 16,
                           vp + (size_t)(j0 + rr) * D3 + c * 8);
        }
    };

    // ---- prologue: stage Q (128 rows) + tile0, then tile1 ----
#pragma unroll
    for (int i = 0; i < 8; i++) {
        int q = tid + 128 * i;                  // 0..1023
        int r = q >> 3, c = q & 7;
        CP_ASYNC16(sb + Q_OFF + r * 144 + c * 16,
                   qp + (size_t)(t0 + r) * D3 + c * 8);
    }
    stage_kv(0, 0);
    CP_COMMIT();
    stage_kv(1, 1);
    CP_COMMIT();

    float oacc[2][8][4];
#pragma unroll
    for (int mt = 0; mt < 2; mt++)
#pragma unroll
        for (int nt = 0; nt < 8; nt++)
#pragma unroll
            for (int c = 0; c < 4; c++) oacc[mt][nt][c] = 0.0f;
    float lacc[2][4];
#pragma unroll
    for (int mt = 0; mt < 2; mt++)
#pragma unroll
        for (int c = 0; c < 4; c++) lacc[mt][c] = 0.0f;
    uint32_t pa_prev[2][16];    // P fragments of tile kt-1, per m-tile
    uint32_t qf[2][4][4];       // Q fragments, resident whole kernel

    const int ntiles = 2 * qb + 2;
    for (int kt = 0; kt < ntiles; kt++) {
        CP_WAIT(1);          // tile kt (and Q on kt=0) complete
        __syncthreads();

        // ---- 0) one-time Q fragment hoist (Q never changes) ----
        if (kt == 0) {
#pragma unroll
            for (int mt = 0; mt < 2; mt++)
#pragma unroll
                for (int kk = 0; kk < 4; kk++)
                    LDSM_X4(qf[mt][kk][0], qf[mt][kk][1], qf[mt][kk][2], qf[mt][kk][3],
                            sb + Q_OFF + (wid * 32 + mt * 16 + lrow) * 144
                               + (kk * 2 + lsel) * 16);
        }

        // ---- 1) deferred O/l += P(kt-1) @ [V(kt-1) | 1]; each V fragment
        //         feeds 4 MMAs (both m-tiles) ----
        if (kt > 0) {
            const uint32_t Vprev = sb + KV_OFF + ((kt - 1) & 3) * 18432 + 9216;
#pragma unroll
            for (int kk = 0; kk < 4; kk++) {
                const uint32_t vaddr = Vprev + (kk * 16 + lrow) * 144 + lsel * 16;
#pragma unroll
                for (int ntp = 0; ntp < 4; ntp++) {
                    uint32_t b0, b1, b2, b3;
                    LDSM_X4_T(b0, b1, b2, b3, vaddr + ntp * 32);
                    uint32_t be[2] = {b0, b1}, bo[2] = {b2, b3};
                    mma16(oacc[0][2 * ntp],     &pa_prev[0][kk * 4], be);
                    mma16(oacc[0][2 * ntp + 1], &pa_prev[0][kk * 4], bo);
                    mma16(oacc[1][2 * ntp],     &pa_prev[1][kk * 4], be);
                    mma16(oacc[1][2 * ntp + 1], &pa_prev[1][kk * 4], bo);
                }
                mma16(lacc[0], &pa_prev[0][kk * 4], bones);
                mma16(lacc[1], &pa_prev[1][kk * 4], bones);
            }
        }

        // ---- 2) stage tile kt+2 (DMA overlaps the QK MMAs below) ----
        if (kt + 2 < ntiles) stage_kv(kt + 2, (kt + 2) & 3);
        CP_COMMIT();

        // ---- 3) S = Q @ K^T; each K fragment feeds 4 MMAs (both m-tiles) ----
        const uint32_t Kb = sb + KV_OFF + (kt & 3) * 18432;
        float sacc[2][8][4];
#pragma unroll
        for (int mt = 0; mt < 2; mt++)
#pragma unroll
            for (int nt = 0; nt < 8; nt++)
#pragma unroll
                for (int c = 0; c < 4; c++) sacc[mt][nt][c] = 0.0f;

#pragma unroll
        for (int kk = 0; kk < 4; kk++) {
            const int cc = (kk * 2 + lsel) * 16;
#pragma unroll
            for (int ntp = 0; ntp < 4; ntp++) {
                uint32_t b0, b1, b2, b3;
                LDSM_X4(b0, b1, b2, b3, Kb + (ntp * 16 + lrow) * 144 + cc);
                uint32_t be[2] = {b0, b2}, bo[2] = {b1, b3};
                mma16(sacc[0][2 * ntp],     qf[0][kk], be);
                mma16(sacc[0][2 * ntp + 1], qf[0][kk], bo);
                mma16(sacc[1][2 * ntp],     qf[1][kk], be);
                mma16(sacc[1][2 * ntp + 1], qf[1][kk], bo);
            }
        }

        // ---- 4) causal mask (last 2 tiles intersect the 128-row diagonal) ----
        if (kt >= ntiles - 2) {
            const int j0 = kt * 64;
#pragma unroll
            for (int mt = 0; mt < 2; mt++) {
                const int r0 = t0 + wid * 32 + mt * 16 + g;
                const int r1 = r0 + 8;
#pragma unroll
                for (int nt = 0; nt < 8; nt++) {
                    int c = j0 + nt * 8 + 2 * tig;
                    if (c     > r0) sacc[mt][nt][0] = -INFINITY;
                    if (c + 1 > r0) sacc[mt][nt][1] = -INFINITY;
                    if (c     > r1) sacc[mt][nt][2] = -INFINITY;
                    if (c + 1 > r1) sacc[mt][nt][3] = -INFINITY;
                }
            }
        }

        // ---- 5) P(kt) = exp2(S) straight into fp16 A-fragments (no max) ----
#pragma unroll
        for (int mt = 0; mt < 2; mt++)
#pragma unroll
            for (int kk = 0; kk < 4; kk++) {
                pa_prev[mt][kk*4+0] = ex2h2(packh2(sacc[mt][2*kk][0],   sacc[mt][2*kk][1]));
                pa_prev[mt][kk*4+1] = ex2h2(packh2(sacc[mt][2*kk][2],   sacc[mt][2*kk][3]));
                pa_prev[mt][kk*4+2] = ex2h2(packh2(sacc[mt][2*kk+1][0], sacc[mt][2*kk+1][1]));
                pa_prev[mt][kk*4+3] = ex2h2(packh2(sacc[mt][2*kk+1][2], sacc[mt][2*kk+1][3]));
            }
    }

    // ---- trailing PV + row sums for the last tile ----
    {
        const uint32_t Vlast = sb + KV_OFF + ((ntiles - 1) & 3) * 18432 + 9216;
#pragma unroll
        for (int kk = 0; kk < 4; kk++) {
            const uint32_t vaddr = Vlast + (kk * 16 + lrow) * 144 + lsel * 16;
#pragma unroll
            for (int ntp = 0; ntp < 4; ntp++) {
                uint32_t b0, b1, b2, b3;
                LDSM_X4_T(b0, b1, b2, b3, vaddr + ntp * 32);
                uint32_t be[2] = {b0, b1}, bo[2] = {b2, b3};
                mma16(oacc[0][2 * ntp],     &pa_prev[0][kk * 4], be);
                mma16(oacc[0][2 * ntp + 1], &pa_prev[0][kk * 4], bo);
                mma16(oacc[1][2 * ntp],     &pa_prev[1][kk * 4], be);
                mma16(oacc[1][2 * ntp + 1], &pa_prev[1][kk * 4], bo);
            }
            mma16(lacc[0], &pa_prev[0][kk * 4], bones);
            mma16(lacc[1], &pa_prev[1][kk * 4], bones);
        }
    }

    // ---- epilogue: normalize, write fp16 [B,T,D] ----
    __half* ob = out + (size_t)b * 4096 * 768;
#pragma unroll
    for (int mt = 0; mt < 2; mt++) {
        const float i0 = 1.0f / lacc[mt][0];
        const float i1 = 1.0f / lacc[mt][2];
        const int r0 = t0 + wid * 32 + mt * 16 + g;
#pragma unroll
        for (int nt = 0; nt < 8; nt++) {
            const int c = h * 64 + nt * 8 + 2 * tig;
            *(uint32_t*)(ob + (size_t)r0 * 768 + c) =
                packh2(oacc[mt][nt][0] * i0, oacc[mt][nt][1] * i0);
            *(uint32_t*)(ob + (size_t)(r0 + 8) * 768 + c) =
                packh2(oacc[mt][nt][2] * i1, oacc[mt][nt][3] * i1);
        }
    }
}

// ---------------------------------------------------------------------------
// Launch
// ---------------------------------------------------------------------------
extern "C" void kernel_launch(void* const* d_in, const int* in_sizes, int n_in,
                              void* d_out, int out_size)
{
    (void)in_sizes; (void)n_in; (void)out_size;
    const float* x     = (const float*)d_in[0];
    const float* Wqkv  = (const float*)d_in[1];
    const float* bqkv  = (const float*)d_in[2];
    const float* Wproj = (const float*)d_in[3];
    const float* bproj = (const float*)d_in[4];
    float* out = (float*)d_out;

    void *pxh, *pwq, *pwp, *pqk, *pat;
    cudaGetSymbolAddress(&pxh, g_xh);
    cudaGetSymbolAddress(&pwq, g_wqh);
    cudaGetSymbolAddress(&pwp, g_wph);
    cudaGetSymbolAddress(&pqk, g_qkvh);
    cudaGetSymbolAddress(&pat, g_atth);
    __half* xh   = (__half*)pxh;
    __half* wqh  = (__half*)pwq;
    __half* wph  = (__half*)pwp;
    __half* qkvh = (__half*)pqk;
    __half* atth = (__half*)pat;

    cudaFuncSetAttribute(gemm_h,
                         cudaFuncAttributeMaxDynamicSharedMemorySize, GEMM_SMEM);
    cudaFuncSetAttribute(flash_h,
                         cudaFuncAttributeMaxDynamicSharedMemorySize, ATT_SMEM);

    // 0) fp16 prep: convert x, transpose+convert weights
    conv_half_k<<<(8192 * 768 / 4 + 255) / 256, 256>>>(x, xh, 8192 * 768 / 4);
    transp_half_k<<<dim3(2304 / 32, 768 / 32), 256>>>(Wqkv,  wqh, 768, 2304);
    transp_half_k<<<dim3(768 / 32,  768 / 32), 256>>>(Wproj, wph, 768, 768);

    // 1) QKV = x @ W_qkv + b_qkv -> fp16 (Q slice pre-scaled by 0.125*log2e)
    gemm_h<<<dim3(2304 / 128, 8192 / 128), 256, GEMM_SMEM>>>(
        xh, wqh, bqkv, nullptr, qkvh, 8192, 2304, 768, 768);

    // 2) causal attention -> fp16 (BM=128, 4 warps x 32 rows, 2 CTAs/SM)
    flash_h<<<dim3(32, 12, 2), 128, ATT_SMEM>>>(qkvh, atth);

    // 3) out = attn @ W_proj + b_proj -> fp32
    gemm_h<<<dim3(768 / 128, 8192 / 128), 256, GEMM_SMEM>>>(
        atth, wph, bproj, out, nullptr, 8192, 768, 768, 0);
}